// round 4
// baseline (speedup 1.0000x reference)
#include <cuda_runtime.h>
#include <cuda_bf16.h>
#include <math.h>

#define NN   4096
#define FF   256
#define ELLW 256
#define TBITS 19
#define TSIZE (1 << TBITS)
#define TMASK (TSIZE - 1)

typedef __nv_bfloat16 bf16;

// ---------------- scratch (device globals) ----------------
__device__ int   g_hkey[TSIZE];
__device__ float g_hvalF[TSIZE];     // weight of direction min->max (and self loops)
__device__ float g_hvalR[TSIZE];     // weight of direction max->min
__device__ float g_deg[NN];
__device__ float g_dinv[NN];
__device__ int   g_cnt[NN];
__device__ int   g_col[NN * ELLW];
__device__ float g_lre[NN * ELLW];
__device__ float g_lim[NN * ELLW];

__device__ float g_Z1r[NN * FF], g_Z1i[NN * FF];
__device__ float g_Z2r[NN * FF], g_Z2i[NN * FF];
__device__ float g_H1r[NN * FF], g_H1i[NN * FF];
__device__ float g_H2r[NN * FF], g_H2i[NN * FF];

// bf16 hi/lo splits of every GEMM operand
__device__ bf16 g_Xrh[NN*FF], g_Xrl[NN*FF], g_Xih[NN*FF], g_Xil[NN*FF];
__device__ bf16 g_Z1rh[NN*FF], g_Z1rl[NN*FF], g_Z1ih[NN*FF], g_Z1il[NN*FF];
__device__ bf16 g_Z2rh[NN*FF], g_Z2rl[NN*FF], g_Z2ih[NN*FF], g_Z2il[NN*FF];
__device__ bf16 g_H1rh[NN*FF], g_H1rl[NN*FF], g_H1ih[NN*FF], g_H1il[NN*FF];
__device__ bf16 g_H2rh[NN*FF], g_H2rl[NN*FF], g_H2ih[NN*FF], g_H2il[NN*FF];
__device__ bf16 g_W1h[3*FF*FF], g_W1l[3*FF*FF], g_W2h[3*FF*FF], g_W2l[3*FF*FF];
__device__ bf16 g_WcTh[512*64], g_WcTl[512*64];
__device__ float g_logits[NN * 64];

__device__ __forceinline__ unsigned hash_key(int key) {
    return ((unsigned)key * 2654435761u) >> (32 - TBITS);
}

// ---------------- graph build ----------------
__global__ void zero_kernel() {
    int idx = blockIdx.x * blockDim.x + threadIdx.x;
    if (idx < TSIZE) { g_hkey[idx] = -1; g_hvalF[idx] = 0.f; g_hvalR[idx] = 0.f; }
    if (idx < NN)    { g_deg[idx] = 0.f; g_cnt[idx] = 0; }
}

__global__ void insert_kernel(const int* __restrict__ edges,
                              const float* __restrict__ w, int E) {
    int e = blockIdx.x * blockDim.x + threadIdx.x;
    if (e >= E) return;
    int r = edges[e];
    int c = edges[E + e];
    float we = w[e];
    atomicAdd(&g_deg[r], 0.5f * we);
    atomicAdd(&g_deg[c], 0.5f * we);
    int lo = min(r, c), hi = max(r, c);
    int key = (lo << 12) | hi;
    unsigned h = hash_key(key) & TMASK;
    while (true) {
        int prev = atomicCAS(&g_hkey[h], -1, key);
        if (prev == -1 || prev == key) {
            if (r <= c) atomicAdd(&g_hvalF[h], we);
            else        atomicAdd(&g_hvalR[h], we);
            break;
        }
        h = (h + 1) & TMASK;
    }
}

__global__ void dinv_kernel() {
    int i = blockIdx.x * blockDim.x + threadIdx.x;
    if (i < NN) {
        float d = g_deg[i];
        if (d == 0.f) d = 1.f;
        g_dinv[i] = rsqrtf(d);
    }
}

__device__ __forceinline__ void ell_push(int r, int c, float lre, float lim) {
    int slot = atomicAdd(&g_cnt[r], 1);
    if (slot < ELLW) {
        g_col[r * ELLW + slot] = c;
        g_lre[r * ELLW + slot] = lre;
        g_lim[r * ELLW + slot] = lim;
    }
}

__global__ void emit_kernel(const float* __restrict__ qp) {
    int s = blockIdx.x * blockDim.x + threadIdx.x;
    if (s >= TSIZE) return;
    int key = g_hkey[s];
    if (key < 0) return;
    int i = key >> 12;         // i <= j
    int j = key & 4095;
    float F = g_hvalF[s];      // A[i][j]
    float R = g_hvalR[s];      // A[j][i]
    float q = __ldg(qp);
    if (i == j) {
        float di = g_dinv[i];
        ell_push(i, i, -di * di * F, 0.f);
        return;
    }
    float asym = 0.5f * (F + R);
    float an = g_dinv[i] * asym * g_dinv[j];
    float th = 6.283185307179586f * q * (F - R);
    float sn, cs;
    sincosf(th, &sn, &cs);
    // conj(L)[i][j] = -A_n * exp(-i*th)
    ell_push(i, j, -an * cs,  an * sn);
    ell_push(j, i, -an * cs, -an * sn);
}

// ---------------- fp32 -> bf16 hi/lo split converters ----------------
__global__ void convert_kernel(const float* __restrict__ in, bf16* __restrict__ hi,
                               bf16* __restrict__ lo, int n) {
    int idx = blockIdx.x * blockDim.x + threadIdx.x;
    if (idx < n) {
        float v = in[idx];
        bf16 h = __float2bfloat16_rn(v);
        hi[idx] = h;
        lo[idx] = __float2bfloat16_rn(v - __bfloat162float(h));
    }
}

// Wc [40][512] -> WcT [512][64] (zero-padded), split
__global__ void convert_wct_kernel(const float* __restrict__ Wc) {
    int idx = blockIdx.x * blockDim.x + threadIdx.x;   // 512*64
    if (idx >= 512 * 64) return;
    int k = idx >> 6, n = idx & 63;
    float v = (n < 40) ? Wc[n * 512 + k] : 0.f;
    bf16 h = __float2bfloat16_rn(v);
    g_WcTh[idx] = h;
    g_WcTl[idx] = __float2bfloat16_rn(v - __bfloat162float(h));
}

// ---------------- complex SpMM (ELL) with split epilogue ----------------
__global__ void spmm_kernel(const float* __restrict__ Xr, const float* __restrict__ Xi,
                            const float* __restrict__ Sr, const float* __restrict__ Si,
                            float* __restrict__ Yr, float* __restrict__ Yi,
                            bf16* __restrict__ Yrh, bf16* __restrict__ Yrl,
                            bf16* __restrict__ Yih, bf16* __restrict__ Yil) {
    int row = blockIdx.x;
    int t = threadIdx.x;
    int cnt = g_cnt[row];
    if (cnt > ELLW) cnt = ELLW;
    __shared__ int   sc[ELLW];
    __shared__ float slr[ELLW];
    __shared__ float sli[ELLW];
    for (int k = t; k < cnt; k += 256) {
        sc [k] = g_col[row * ELLW + k];
        slr[k] = g_lre[row * ELLW + k];
        sli[k] = g_lim[row * ELLW + k];
    }
    __syncthreads();
    float ar = 0.f, ai = 0.f;
    #pragma unroll 4
    for (int k = 0; k < cnt; k++) {
        int   c  = sc[k];
        float lr = slr[k];
        float li = sli[k];
        float xr = __ldg(&Xr[c * FF + t]);
        float xi = __ldg(&Xi[c * FF + t]);
        ar = fmaf(lr, xr, ar);
        ar = fmaf(-li, xi, ar);
        ai = fmaf(lr, xi, ai);
        ai = fmaf(li, xr, ai);
    }
    int o = row * FF + t;
    float yr, yi;
    if (Sr) {
        yr = 2.f * ar - Sr[o];
        yi = 2.f * ai - Si[o];
    } else {
        yr = ar;
        yi = ai;
    }
    Yr[o] = yr;
    Yi[o] = yi;
    bf16 hr = __float2bfloat16_rn(yr);
    bf16 hi = __float2bfloat16_rn(yi);
    Yrh[o] = hr;  Yrl[o] = __float2bfloat16_rn(yr - __bfloat162float(hr));
    Yih[o] = hi;  Yil[o] = __float2bfloat16_rn(yi - __bfloat162float(hi));
}

// ---------------- tensor-core GEMM machinery ----------------
__device__ __forceinline__ unsigned pack_bf2(float x, float y) {
    __nv_bfloat162 t;
    t.x = __float2bfloat16_rn(x);
    t.y = __float2bfloat16_rn(y);
    return *reinterpret_cast<unsigned*>(&t);
}

#define MMA_BF16(d, a, b)                                                        \
    asm volatile("mma.sync.aligned.m16n8k16.row.col.f32.bf16.bf16.f32 "          \
                 "{%0,%1,%2,%3},{%4,%5,%6,%7},{%8,%9},{%0,%1,%2,%3};"            \
                 : "+f"(d[0]), "+f"(d[1]), "+f"(d[2]), "+f"(d[3])                 \
                 : "r"(a[0]), "r"(a[1]), "r"(a[2]), "r"(a[3]), "r"(b[0]), "r"(b[1]))

#define LDSM_X4(r, addr)                                                         \
    asm volatile("ldmatrix.sync.aligned.m8n8.x4.shared.b16 {%0,%1,%2,%3}, [%4];" \
                 : "=r"(r[0]), "=r"(r[1]), "=r"(r[2]), "=r"(r[3]) : "r"(addr) : "memory")

#define LDSM_X4_T(r, addr)                                                             \
    asm volatile("ldmatrix.sync.aligned.m8n8.x4.trans.shared.b16 {%0,%1,%2,%3}, [%4];" \
                 : "=r"(r[0]), "=r"(r[1]), "=r"(r[2]), "=r"(r[3]) : "r"(addr) : "memory")

__device__ __forceinline__ void cp16(unsigned dst, const void* src) {
    asm volatile("cp.async.cg.shared.global [%0], [%1], 16;\n" :: "r"(dst), "l"(src));
}
__device__ __forceinline__ void cp_commit() {
    asm volatile("cp.async.commit_group;\n" ::: "memory");
}
__device__ __forceinline__ void cp_wait1() {
    asm volatile("cp.async.wait_group 1;\n" ::: "memory");
}

// smem stage layout (bytes): A rows pitch 80 (64B data + 16 pad), W rows pitch 144
#define A_HI_OFF   0
#define A_LO_OFF   10240
#define W_HI_OFF   20480
#define W_LO_OFF   25088
#define STAGE_SZ   29696
#define GEMM_SMEM  (2 * STAGE_SZ)

struct GemmArgs {
    const bf16* Ah[6];   // [0..2]=real planes, [3..5]=imag planes
    const bf16* Al[6];
    const bf16* Wh;
    const bf16* Wl;
    const float* bias;
    float* Hr;
    float* Hi;
    bf16 *Hrh, *Hrl, *Hih, *Hil;
};

__device__ __forceinline__ void gemm_load_stage(unsigned sbase,
        const bf16* Ah, const bf16* Al, const bf16* Wh, const bf16* Wl,
        int a_row0, int kc, long w_row0, int n0, int tid) {
    #pragma unroll
    for (int it = 0; it < 2; it++) {
        int idx = tid + it * 256;          // 0..511
        int r = idx >> 2, c = idx & 3;
        const char* srcH = (const char*)(Ah + (long)(a_row0 + r) * 256 + kc) + c * 16;
        const char* srcL = (const char*)(Al + (long)(a_row0 + r) * 256 + kc) + c * 16;
        cp16(sbase + A_HI_OFF + r * 80 + c * 16, srcH);
        cp16(sbase + A_LO_OFF + r * 80 + c * 16, srcL);
    }
    {
        int r = tid >> 3, c = tid & 7;     // 32 rows x 8 chunks (128B per row)
        const char* srcH = (const char*)(Wh + (w_row0 + r) * 256 + n0) + c * 16;
        const char* srcL = (const char*)(Wl + (w_row0 + r) * 256 + n0) + c * 16;
        cp16(sbase + W_HI_OFF + r * 144 + c * 16, srcH);
        cp16(sbase + W_LO_OFF + r * 144 + c * 16, srcL);
    }
}

__device__ __forceinline__ void gemm_mma_stage(unsigned sbase, unsigned a_off, unsigned w_off,
                                               float acc[4][2][4]) {
    #pragma unroll
    for (int h = 0; h < 32; h += 16) {
        unsigned ah[4][4], al[4][4];
        #pragma unroll
        for (int mt = 0; mt < 4; mt++) {
            unsigned off = a_off + mt * 16 * 80 + h * 2;
            LDSM_X4(ah[mt], sbase + A_HI_OFF + off);
            LDSM_X4(al[mt], sbase + A_LO_OFF + off);
        }
        unsigned bh4[4], bl4[4];
        {
            unsigned off = w_off + h * 144;
            LDSM_X4_T(bh4, sbase + W_HI_OFF + off);
            LDSM_X4_T(bl4, sbase + W_LO_OFF + off);
        }
        #pragma unroll
        for (int mt = 0; mt < 4; mt++) {
            #pragma unroll
            for (int nt = 0; nt < 2; nt++) {
                unsigned bh[2] = {bh4[nt * 2], bh4[nt * 2 + 1]};
                unsigned bl[2] = {bl4[nt * 2], bl4[nt * 2 + 1]};
                MMA_BF16(acc[mt][nt], ah[mt], bh);
                MMA_BF16(acc[mt][nt], ah[mt], bl);
                MMA_BF16(acc[mt][nt], al[mt], bh);
            }
        }
    }
}

// C[8192,256] = [Zr;Zi] @ Wcat ; rows<4096 -> Hi=+C+b ; rows>=4096 -> Hr=-C+b
__global__ void __launch_bounds__(256, 2)
gemm_fused_kernel(GemmArgs ga) {
    extern __shared__ char dynsmem[];
    unsigned sm0 = (unsigned)__cvta_generic_to_shared(dynsmem);

    int tid = threadIdx.x;
    int lane = tid & 31;
    int warp = tid >> 5;
    int wm = warp >> 2;
    int wn = warp & 3;
    int m0 = blockIdx.y * 128;
    int n0 = blockIdx.x * 64;
    bool isImag = (m0 >= 4096);
    int mrow0 = m0 & 4095;
    int pbase = isImag ? 3 : 0;

    float acc[4][2][4];
    #pragma unroll
    for (int mt = 0; mt < 4; mt++)
        #pragma unroll
        for (int nt = 0; nt < 2; nt++)
            #pragma unroll
            for (int r = 0; r < 4; r++) acc[mt][nt][r] = 0.f;

    unsigned a_off = (wm * 64 + (lane & 15)) * 80 + (lane >> 4) * 16;
    unsigned w_off = (((lane >> 3) & 1) * 8 + (lane & 7)) * 144 + wn * 32 + (lane >> 4) * 16;

    // prologue: stage 0
    gemm_load_stage(sm0, ga.Ah[pbase], ga.Al[pbase], ga.Wh, ga.Wl, mrow0, 0, 0, n0, tid);
    cp_commit();

    for (int ks = 0; ks < 24; ks++) {
        int nst = ks + 1;
        if (nst < 24) {
            int plane = nst >> 3;
            int kc = (nst & 7) * 32;
            unsigned sb = sm0 + (nst & 1) * STAGE_SZ;
            gemm_load_stage(sb, ga.Ah[pbase + plane], ga.Al[pbase + plane],
                            ga.Wh, ga.Wl, mrow0, kc, (long)plane * 256 + kc, n0, tid);
        }
        cp_commit();
        cp_wait1();
        __syncthreads();
        gemm_mma_stage(sm0 + (ks & 1) * STAGE_SZ, a_off, w_off, acc);
        __syncthreads();
    }

    // epilogue
    int g = lane >> 2, tig = lane & 3;
    float sign = isImag ? -1.f : 1.f;
    float* Fd        = isImag ? ga.Hr  : ga.Hi;
    bf16*  Hh        = isImag ? ga.Hrh : ga.Hih;
    bf16*  Hl        = isImag ? ga.Hrl : ga.Hil;
    #pragma unroll
    for (int mt = 0; mt < 4; mt++) {
        #pragma unroll
        for (int nt = 0; nt < 2; nt++) {
            int n = n0 + wn * 16 + nt * 8 + tig * 2;
            float b0 = ga.bias[n], b1v = ga.bias[n + 1];
            int ml0 = mrow0 + wm * 64 + mt * 16 + g;
            float* c0 = acc[mt][nt];
            #pragma unroll
            for (int half = 0; half < 2; half++) {
                int idx = (ml0 + half * 8) * 256 + n;
                float va = sign * c0[half * 2]     + b0;
                float vb = sign * c0[half * 2 + 1] + b1v;
                *reinterpret_cast<float2*>(&Fd[idx]) = make_float2(va, vb);
                bf16 ha = __float2bfloat16_rn(va);
                bf16 hb = __float2bfloat16_rn(vb);
                float la = va - __bfloat162float(ha);
                float lb = vb - __bfloat162float(hb);
                *reinterpret_cast<unsigned*>(&Hh[idx]) = pack_bf2(va, vb);
                *reinterpret_cast<unsigned*>(&Hl[idx]) = pack_bf2(la, lb);
            }
        }
    }
}

// logits[4096,64] = [Hr|Hi](4096x512) @ WcT(512x64)
__global__ void __launch_bounds__(256, 2)
cls_gemm_kernel(const bf16* __restrict__ A0h, const bf16* __restrict__ A0l,
                const bf16* __restrict__ A1h, const bf16* __restrict__ A1l,
                const bf16* __restrict__ Wh,  const bf16* __restrict__ Wl,
                float* __restrict__ out) {
    extern __shared__ char dynsmem[];
    unsigned sm0 = (unsigned)__cvta_generic_to_shared(dynsmem);

    int tid = threadIdx.x;
    int lane = tid & 31;
    int warp = tid >> 5;
    int wm = warp >> 2;
    int wn = warp & 3;
    int mrow0 = blockIdx.y * 128;
    int n0 = blockIdx.x * 64;

    float acc[4][2][4];
    #pragma unroll
    for (int mt = 0; mt < 4; mt++)
        #pragma unroll
        for (int nt = 0; nt < 2; nt++)
            #pragma unroll
            for (int r = 0; r < 4; r++) acc[mt][nt][r] = 0.f;

    unsigned a_off = (wm * 64 + (lane & 15)) * 80 + (lane >> 4) * 16;
    unsigned w_off = (((lane >> 3) & 1) * 8 + (lane & 7)) * 144 + wn * 32 + (lane >> 4) * 16;

    // W tile loader: WcT is [512][64] (pitch 64 elems = 128B per row, 8 chunks)
    auto load_stage = [&](unsigned sbase, const bf16* Ah, const bf16* Al, int kc, int kglob) {
        #pragma unroll
        for (int it = 0; it < 2; it++) {
            int idx = tid + it * 256;
            int r = idx >> 2, c = idx & 3;
            const char* srcH = (const char*)(Ah + (long)(mrow0 + r) * 256 + kc) + c * 16;
            const char* srcL = (const char*)(Al + (long)(mrow0 + r) * 256 + kc) + c * 16;
            cp16(sbase + A_HI_OFF + r * 80 + c * 16, srcH);
            cp16(sbase + A_LO_OFF + r * 80 + c * 16, srcL);
        }
        {
            int r = tid >> 3, c = tid & 7;   // 32 rows x 8 chunks of 16B = 128B/row
            const char* srcH = (const char*)(Wh + (long)(kglob + r) * 64) + c * 16;
            const char* srcL = (const char*)(Wl + (long)(kglob + r) * 64) + c * 16;
            cp16(sbase + W_HI_OFF + r * 144 + c * 16, srcH);
            cp16(sbase + W_LO_OFF + r * 144 + c * 16, srcL);
        }
    };

    load_stage(sm0, A0h, A0l, 0, 0);
    cp_commit();
    for (int ks = 0; ks < 16; ks++) {
        int nst = ks + 1;
        if (nst < 16) {
            int plane = nst >> 3;
            int kc = (nst & 7) * 32;
            load_stage(sm0 + (nst & 1) * STAGE_SZ, plane ? A1h : A0h, plane ? A1l : A0l,
                       kc, plane * 256 + kc);
        }
        cp_commit();
        cp_wait1();
        __syncthreads();
        gemm_mma_stage(sm0 + (ks & 1) * STAGE_SZ, a_off, w_off, acc);
        __syncthreads();
    }

    int g = lane >> 2, tig = lane & 3;
    #pragma unroll
    for (int mt = 0; mt < 4; mt++) {
        #pragma unroll
        for (int nt = 0; nt < 2; nt++) {
            int n = n0 + wn * 16 + nt * 8 + tig * 2;
            int ml0 = mrow0 + wm * 64 + mt * 16 + g;
            float* c0 = acc[mt][nt];
            *reinterpret_cast<float2*>(&out[ml0 * 64 + n])       = make_float2(c0[0], c0[1]);
            *reinterpret_cast<float2*>(&out[(ml0 + 8) * 64 + n]) = make_float2(c0[2], c0[3]);
        }
    }
}

// log_softmax over first 40 cols of logits (+bias), one warp per row
__global__ void logsoftmax_kernel(const float* __restrict__ logits,
                                  const float* __restrict__ bc,
                                  float* __restrict__ out) {
    int warp = threadIdx.x >> 5, lane = threadIdx.x & 31;
    int row = blockIdx.x * 8 + warp;
    float a  = (lane < 40)      ? logits[row * 64 + lane]      + bc[lane]      : -3.4e38f;
    float b2 = (lane + 32 < 40) ? logits[row * 64 + lane + 32] + bc[lane + 32] : -3.4e38f;
    float m = fmaxf(a, b2);
    #pragma unroll
    for (int o = 16; o > 0; o >>= 1) m = fmaxf(m, __shfl_xor_sync(0xffffffffu, m, o));
    float s = ((lane < 40) ? expf(a - m) : 0.f) + ((lane + 32 < 40) ? expf(b2 - m) : 0.f);
    #pragma unroll
    for (int o = 16; o > 0; o >>= 1) s += __shfl_xor_sync(0xffffffffu, s, o);
    float lse = m + logf(s);
    if (lane < 40)      out[row * 40 + lane]      = a - lse;
    if (lane + 32 < 40) out[row * 40 + lane + 32] = b2 - lse;
}

// ---------------- launch ----------------
extern "C" void kernel_launch(void* const* d_in, const int* in_sizes, int n_in,
                              void* d_out, int out_size) {
    const float* real = (const float*)d_in[0];
    const float* imag = (const float*)d_in[1];
    const int*   edges = (const int*)d_in[2];
    const float* qp = (const float*)d_in[3];
    const float* ew = (const float*)d_in[4];
    const float* W1 = (const float*)d_in[5];
    const float* b1 = (const float*)d_in[6];
    const float* W2 = (const float*)d_in[7];
    const float* b2 = (const float*)d_in[8];
    const float* Wc = (const float*)d_in[9];
    const float* bc = (const float*)d_in[10];
    float* out = (float*)d_out;
    int E = in_sizes[4];

    cudaFuncSetAttribute(gemm_fused_kernel, cudaFuncAttributeMaxDynamicSharedMemorySize, GEMM_SMEM);
    cudaFuncSetAttribute(cls_gemm_kernel,   cudaFuncAttributeMaxDynamicSharedMemorySize, GEMM_SMEM);

    #define GET(p, s) cudaGetSymbolAddress((void**)&p, s)
    float *Z1r, *Z1i, *Z2r, *Z2i, *H1r, *H1i, *H2r, *H2i, *logits;
    GET(Z1r, g_Z1r); GET(Z1i, g_Z1i); GET(Z2r, g_Z2r); GET(Z2i, g_Z2i);
    GET(H1r, g_H1r); GET(H1i, g_H1i); GET(H2r, g_H2r); GET(H2i, g_H2i);
    GET(logits, g_logits);
    bf16 *Xrh,*Xrl,*Xih,*Xil, *Z1rh,*Z1rl,*Z1ih,*Z1il, *Z2rh,*Z2rl,*Z2ih,*Z2il;
    bf16 *H1rh,*H1rl,*H1ih,*H1il, *H2rh,*H2rl,*H2ih,*H2il;
    bf16 *W1h,*W1l,*W2h,*W2l, *WcTh,*WcTl;
    GET(Xrh, g_Xrh); GET(Xrl, g_Xrl); GET(Xih, g_Xih); GET(Xil, g_Xil);
    GET(Z1rh, g_Z1rh); GET(Z1rl, g_Z1rl); GET(Z1ih, g_Z1ih); GET(Z1il, g_Z1il);
    GET(Z2rh, g_Z2rh); GET(Z2rl, g_Z2rl); GET(Z2ih, g_Z2ih); GET(Z2il, g_Z2il);
    GET(H1rh, g_H1rh); GET(H1rl, g_H1rl); GET(H1ih, g_H1ih); GET(H1il, g_H1il);
    GET(H2rh, g_H2rh); GET(H2rl, g_H2rl); GET(H2ih, g_H2ih); GET(H2il, g_H2il);
    GET(W1h, g_W1h); GET(W1l, g_W1l); GET(W2h, g_W2h); GET(W2l, g_W2l);
    GET(WcTh, g_WcTh); GET(WcTl, g_WcTl);
    #undef GET

    // graph build
    zero_kernel<<<TSIZE / 256, 256>>>();
    insert_kernel<<<(E + 255) / 256, 256>>>(edges, ew, E);
    dinv_kernel<<<NN / 256, 256>>>();
    emit_kernel<<<TSIZE / 256, 256>>>(qp);

    // operand conversions
    convert_kernel<<<(NN * FF) / 256, 256>>>(real, Xrh, Xrl, NN * FF);
    convert_kernel<<<(NN * FF) / 256, 256>>>(imag, Xih, Xil, NN * FF);
    convert_kernel<<<(3 * FF * FF + 255) / 256, 256>>>(W1, W1h, W1l, 3 * FF * FF);
    convert_kernel<<<(3 * FF * FF + 255) / 256, 256>>>(W2, W2h, W2l, 3 * FF * FF);
    convert_wct_kernel<<<(512 * 64) / 256, 256>>>(Wc);

    // ---- layer 1 ----
    spmm_kernel<<<NN, 256>>>(real, imag, nullptr, nullptr, Z1r, Z1i, Z1rh, Z1rl, Z1ih, Z1il);
    spmm_kernel<<<NN, 256>>>(Z1r, Z1i, real, imag, Z2r, Z2i, Z2rh, Z2rl, Z2ih, Z2il);
    {
        GemmArgs ga;
        ga.Ah[0]=Xrh; ga.Ah[1]=Z1rh; ga.Ah[2]=Z2rh; ga.Ah[3]=Xih; ga.Ah[4]=Z1ih; ga.Ah[5]=Z2ih;
        ga.Al[0]=Xrl; ga.Al[1]=Z1rl; ga.Al[2]=Z2rl; ga.Al[3]=Xil; ga.Al[4]=Z1il; ga.Al[5]=Z2il;
        ga.Wh=W1h; ga.Wl=W1l; ga.bias=b1; ga.Hr=H1r; ga.Hi=H1i;
        ga.Hrh=H1rh; ga.Hrl=H1rl; ga.Hih=H1ih; ga.Hil=H1il;
        gemm_fused_kernel<<<dim3(4, 64), 256, GEMM_SMEM>>>(ga);
    }

    // ---- layer 2 ----
    spmm_kernel<<<NN, 256>>>(H1r, H1i, nullptr, nullptr, Z1r, Z1i, Z1rh, Z1rl, Z1ih, Z1il);
    spmm_kernel<<<NN, 256>>>(Z1r, Z1i, H1r, H1i, Z2r, Z2i, Z2rh, Z2rl, Z2ih, Z2il);
    {
        GemmArgs ga;
        ga.Ah[0]=H1rh; ga.Ah[1]=Z1rh; ga.Ah[2]=Z2rh; ga.Ah[3]=H1ih; ga.Ah[4]=Z1ih; ga.Ah[5]=Z2ih;
        ga.Al[0]=H1rl; ga.Al[1]=Z1rl; ga.Al[2]=Z2rl; ga.Al[3]=H1il; ga.Al[4]=Z1il; ga.Al[5]=Z2il;
        ga.Wh=W2h; ga.Wl=W2l; ga.bias=b2; ga.Hr=H2r; ga.Hi=H2i;
        ga.Hrh=H2rh; ga.Hrl=H2rl; ga.Hih=H2ih; ga.Hil=H2il;
        gemm_fused_kernel<<<dim3(4, 64), 256, GEMM_SMEM>>>(ga);
    }

    // ---- classifier ----
    cls_gemm_kernel<<<dim3(1, 32), 256, GEMM_SMEM>>>(H2rh, H2rl, H2ih, H2il, WcTh, WcTl, logits);
    logsoftmax_kernel<<<NN / 8, 256>>>(logits, bc, out);
}

// round 7
// speedup vs baseline: 1.0498x; 1.0498x over previous
#include <cuda_runtime.h>
#include <cuda_bf16.h>
#include <math.h>

#define NN   4096
#define FF   256
#define ELLW 256
#define TBITS 18
#define TSIZE (1 << TBITS)
#define TMASK (TSIZE - 1)
#define EMAX  131072

// ---------------- scratch (device globals) ----------------
__device__ int   g_hkey[TSIZE];
__device__ float g_hvalF[TSIZE];     // weight of direction min->max (and self loops)
__device__ float g_hvalR[TSIZE];     // weight of direction max->min
__device__ int   g_plist[EMAX];      // compacted list of claimed slots
__device__ int   g_np;
__device__ float g_deg[NN];
__device__ float g_dinv[NN];
__device__ int   g_cnt[NN];
__device__ int   g_col[NN * ELLW];
__device__ float g_lre[NN * ELLW];
__device__ float g_lim[NN * ELLW];
__device__ float g_Z1r[NN * FF], g_Z1i[NN * FF];
__device__ float g_Z2r[NN * FF], g_Z2i[NN * FF];
__device__ float g_H1r[NN * FF], g_H1i[NN * FF];
__device__ float g_H2r[NN * FF], g_H2i[NN * FF];

__device__ __forceinline__ unsigned hash_key(int key) {
    return ((unsigned)key * 2654435761u) >> (32 - TBITS);
}

// ---------------- graph build ----------------
__global__ void zero_kernel() {
    int idx = blockIdx.x * blockDim.x + threadIdx.x;
    if (idx < TSIZE) { g_hkey[idx] = -1; g_hvalF[idx] = 0.f; g_hvalR[idx] = 0.f; }
    if (idx < NN)    { g_deg[idx] = 0.f; g_cnt[idx] = 0; }
    if (idx == 0)    g_np = 0;
}

__global__ void insert_kernel(const int* __restrict__ edges,
                              const float* __restrict__ w, int E) {
    int e = blockIdx.x * blockDim.x + threadIdx.x;
    if (e >= E) return;
    int r = edges[e];
    int c = edges[E + e];
    float we = w[e];
    atomicAdd(&g_deg[r], 0.5f * we);
    atomicAdd(&g_deg[c], 0.5f * we);
    int lo = min(r, c), hi = max(r, c);
    int key = (lo << 12) | hi;
    unsigned h = hash_key(key) & TMASK;
    while (true) {
        int prev = atomicCAS(&g_hkey[h], -1, key);
        if (prev == -1 || prev == key) {
            if (prev == -1) {
                int pos = atomicAdd(&g_np, 1);
                g_plist[pos] = (int)h;
            }
            if (r <= c) atomicAdd(&g_hvalF[h], we);
            else        atomicAdd(&g_hvalR[h], we);
            break;
        }
        h = (h + 1) & TMASK;
    }
}

__global__ void dinv_kernel() {
    int i = blockIdx.x * blockDim.x + threadIdx.x;
    if (i < NN) {
        float d = g_deg[i];
        if (d == 0.f) d = 1.f;
        g_dinv[i] = rsqrtf(d);
    }
}

__device__ __forceinline__ void ell_push(int r, int c, float lre, float lim) {
    int slot = atomicAdd(&g_cnt[r], 1);
    if (slot < ELLW) {
        g_col[r * ELLW + slot] = c;
        g_lre[r * ELLW + slot] = lre;
        g_lim[r * ELLW + slot] = lim;
    }
}

// scan only the compacted claimed-slot list (no empty-slot scan)
__global__ void emit_kernel(const float* __restrict__ qp) {
    int idx = blockIdx.x * blockDim.x + threadIdx.x;
    if (idx >= g_np) return;
    int s = g_plist[idx];
    int key = g_hkey[s];
    int i = key >> 12;         // i <= j
    int j = key & 4095;
    float F = g_hvalF[s];      // A[i][j]
    float R = g_hvalR[s];      // A[j][i]
    float q = __ldg(qp);
    if (i == j) {
        float di = g_dinv[i];
        ell_push(i, i, -di * di * F, 0.f);
        return;
    }
    float asym = 0.5f * (F + R);
    float an = g_dinv[i] * asym * g_dinv[j];
    float th = 6.283185307179586f * q * (F - R);
    float sn, cs;
    sincosf(th, &sn, &cs);
    // conj(L)[i][j] = -A_n * exp(-i*th)
    ell_push(i, j, -an * cs,  an * sn);
    ell_push(j, i, -an * cs, -an * sn);
}

// ---------------- complex SpMM (ELL) ----------------
__global__ void spmm_kernel(const float* __restrict__ Xr, const float* __restrict__ Xi,
                            const float* __restrict__ Sr, const float* __restrict__ Si,
                            float* __restrict__ Yr, float* __restrict__ Yi) {
    int row = blockIdx.x;
    int t = threadIdx.x;
    int cnt = g_cnt[row];
    if (cnt > ELLW) cnt = ELLW;
    __shared__ int   sc[ELLW];
    __shared__ float slr[ELLW];
    __shared__ float sli[ELLW];
    for (int k = t; k < cnt; k += 256) {
        sc [k] = g_col[row * ELLW + k];
        slr[k] = g_lre[row * ELLW + k];
        sli[k] = g_lim[row * ELLW + k];
    }
    __syncthreads();
    float ar = 0.f, ai = 0.f;
    #pragma unroll 4
    for (int k = 0; k < cnt; k++) {
        int   c  = sc[k];
        float lr = slr[k];
        float li = sli[k];
        float xr = __ldg(&Xr[c * FF + t]);
        float xi = __ldg(&Xi[c * FF + t]);
        ar = fmaf(lr, xr, ar);
        ar = fmaf(-li, xi, ar);
        ai = fmaf(lr, xi, ai);
        ai = fmaf(li, xr, ai);
    }
    int o = row * FF + t;
    if (Sr) {
        Yr[o] = 2.f * ar - Sr[o];
        Yi[o] = 2.f * ai - Si[o];
    } else {
        Yr[o] = ar;
        Yi[o] = ai;
    }
}

// ---------------- fused tensor-core GEMM (bf16 3-term split, inline convert) ----------------
// C[8192,256] = [Zr;Zi](8192x768) @ Wcat(768x256); rows<4096 -> Hi=C+b, rows>=4096 -> Hr=-C+b
// BM=128, BN=64, BK=32; 256 thr = 8 warps (2m x 4n); warp tile 64x16.

__device__ __forceinline__ unsigned pack_bf2(float x, float y) {
    __nv_bfloat162 t;
    t.x = __float2bfloat16_rn(x);
    t.y = __float2bfloat16_rn(y);
    return *reinterpret_cast<unsigned*>(&t);
}

#define MMA_BF16(d, a, b)                                                        \
    asm volatile("mma.sync.aligned.m16n8k16.row.col.f32.bf16.bf16.f32 "          \
                 "{%0,%1,%2,%3},{%4,%5,%6,%7},{%8,%9},{%0,%1,%2,%3};"            \
                 : "+f"(d[0]), "+f"(d[1]), "+f"(d[2]), "+f"(d[3])                 \
                 : "r"(a[0]), "r"(a[1]), "r"(a[2]), "r"(a[3]), "r"(b[0]), "r"(b[1]))

#define LDSM_X4(r, addr)                                                         \
    asm volatile("ldmatrix.sync.aligned.m8n8.x4.shared.b16 {%0,%1,%2,%3}, [%4];" \
                 : "=r"(r[0]), "=r"(r[1]), "=r"(r[2]), "=r"(r[3]) : "r"(addr) : "memory")

#define LDSM_X4_T(r, addr)                                                             \
    asm volatile("ldmatrix.sync.aligned.m8n8.x4.trans.shared.b16 {%0,%1,%2,%3}, [%4];" \
                 : "=r"(r[0]), "=r"(r[1]), "=r"(r[2]), "=r"(r[3]) : "r"(addr) : "memory")

#define AST 20   // A smem row stride in uints (40 bf16 = 80B, LDSM conflict-free)
#define WST 36   // W smem row stride in uints (72 bf16 = 144B, LDSM.T conflict-free)

__global__ void __launch_bounds__(256, 2)
gemm_fused_kernel(const float* __restrict__ A0r, const float* __restrict__ A1r,
                  const float* __restrict__ A2r, const float* __restrict__ A0i,
                  const float* __restrict__ A1i, const float* __restrict__ A2i,
                  const float* __restrict__ W, const float* __restrict__ bias,
                  float* __restrict__ Hr, float* __restrict__ Hi) {
    __shared__ unsigned ash[128 * AST], asl[128 * AST];
    __shared__ unsigned wsh[32 * WST],  wsl[32 * WST];

    int tid = threadIdx.x;
    int lane = tid & 31;
    int warp = tid >> 5;
    int wm = warp >> 2;          // 0..1
    int wn = warp & 3;           // 0..3
    int m0 = blockIdx.y * 128;   // 0..8064
    int n0 = blockIdx.x * 64;
    bool isImag = (m0 >= 4096);
    int mrow0 = m0 & 4095;

    float acc[4][2][4];
    #pragma unroll
    for (int mt = 0; mt < 4; mt++)
        #pragma unroll
        for (int nt = 0; nt < 2; nt++)
            #pragma unroll
            for (int r = 0; r < 4; r++) acc[mt][nt][r] = 0.f;

    unsigned a_hi_base = (unsigned)__cvta_generic_to_shared(ash);
    unsigned a_lo_base = (unsigned)__cvta_generic_to_shared(asl);
    unsigned w_hi_base = (unsigned)__cvta_generic_to_shared(wsh);
    unsigned w_lo_base = (unsigned)__cvta_generic_to_shared(wsl);

    // per-lane LDSM byte offsets (h added later)
    unsigned a_off = ((wm * 64 + (lane & 15)) * (AST * 2) + (lane >> 4) * 8) * 2;
    unsigned w_off = (((((lane >> 3) & 1) * 8 + (lane & 7)) * (WST * 2)) + wn * 16 + (lane >> 4) * 8) * 2;

    for (int ks = 0; ks < 24; ks++) {
        int k0 = ks * 32;
        int plane = k0 >> 8;
        int kc = k0 & 255;
        const float* Ap = isImag ? (plane == 0 ? A0i : (plane == 1 ? A1i : A2i))
                                 : (plane == 0 ? A0r : (plane == 1 ? A1r : A2r));
        // load A tile 128x32
        #pragma unroll
        for (int t = 0; t < 4; t++) {
            int idx = tid + t * 256;
            int r = idx >> 3;
            int c4 = (idx & 7) * 4;
            float4 v = *reinterpret_cast<const float4*>(&Ap[(mrow0 + r) * 256 + kc + c4]);
            float hx = __bfloat162float(__float2bfloat16_rn(v.x));
            float hy = __bfloat162float(__float2bfloat16_rn(v.y));
            float hz = __bfloat162float(__float2bfloat16_rn(v.z));
            float hw = __bfloat162float(__float2bfloat16_rn(v.w));
            int o = r * AST + (c4 >> 1);
            ash[o]     = pack_bf2(v.x, v.y);
            ash[o + 1] = pack_bf2(v.z, v.w);
            asl[o]     = pack_bf2(v.x - hx, v.y - hy);
            asl[o + 1] = pack_bf2(v.z - hz, v.w - hw);
        }
        // load W tile 32x64 (k-major): 2 iters x 256 thr x float4 = 2048 elems
        #pragma unroll
        for (int t = 0; t < 2; t++) {
            int idx = tid + t * 256;
            int kk = idx >> 4;          // 0..31
            int n4 = (idx & 15) * 4;    // 0..60
            float4 v = *reinterpret_cast<const float4*>(&W[plane * 65536 + (kc + kk) * 256 + n0 + n4]);
            float hx = __bfloat162float(__float2bfloat16_rn(v.x));
            float hy = __bfloat162float(__float2bfloat16_rn(v.y));
            float hz = __bfloat162float(__float2bfloat16_rn(v.z));
            float hw = __bfloat162float(__float2bfloat16_rn(v.w));
            int o = kk * WST + (n4 >> 1);
            wsh[o]     = pack_bf2(v.x, v.y);
            wsh[o + 1] = pack_bf2(v.z, v.w);
            wsl[o]     = pack_bf2(v.x - hx, v.y - hy);
            wsl[o + 1] = pack_bf2(v.z - hz, v.w - hw);
        }
        __syncthreads();

        #pragma unroll
        for (int h = 0; h < 32; h += 16) {
            unsigned ah[4][4], al[4][4];
            #pragma unroll
            for (int mt = 0; mt < 4; mt++) {
                unsigned off = a_off + (mt * 16 * AST * 2 + h) * 2;
                LDSM_X4(ah[mt], a_hi_base + off);
                LDSM_X4(al[mt], a_lo_base + off);
            }
            unsigned bh4[4], bl4[4];
            {
                unsigned off = w_off + (h * WST * 2) * 2;
                LDSM_X4_T(bh4, w_hi_base + off);
                LDSM_X4_T(bl4, w_lo_base + off);
            }
            #pragma unroll
            for (int mt = 0; mt < 4; mt++) {
                #pragma unroll
                for (int nt = 0; nt < 2; nt++) {
                    unsigned bh[2] = {bh4[nt * 2], bh4[nt * 2 + 1]};
                    unsigned bl[2] = {bl4[nt * 2], bl4[nt * 2 + 1]};
                    MMA_BF16(acc[mt][nt], ah[mt], bh);
                    MMA_BF16(acc[mt][nt], ah[mt], bl);
                    MMA_BF16(acc[mt][nt], al[mt], bh);
                }
            }
        }
        __syncthreads();
    }

    // epilogue
    int g = lane >> 2, tig = lane & 3;
    #pragma unroll
    for (int mt = 0; mt < 4; mt++) {
        #pragma unroll
        for (int nt = 0; nt < 2; nt++) {
            int n = n0 + wn * 16 + nt * 8 + tig * 2;
            float b0 = bias[n], b1v = bias[n + 1];
            int ml0 = mrow0 + wm * 64 + mt * 16 + g;
            float* c0 = acc[mt][nt];
            if (!isImag) {
                float2 o0 = make_float2(c0[0] + b0, c0[1] + b1v);
                float2 o1 = make_float2(c0[2] + b0, c0[3] + b1v);
                *reinterpret_cast<float2*>(&Hi[ml0 * 256 + n])       = o0;
                *reinterpret_cast<float2*>(&Hi[(ml0 + 8) * 256 + n]) = o1;
            } else {
                float2 o0 = make_float2(-c0[0] + b0, -c0[1] + b1v);
                float2 o1 = make_float2(-c0[2] + b0, -c0[3] + b1v);
                *reinterpret_cast<float2*>(&Hr[ml0 * 256 + n])       = o0;
                *reinterpret_cast<float2*>(&Hr[(ml0 + 8) * 256 + n]) = o1;
            }
        }
    }
}

// ---------------- classifier + log_softmax ----------------
__global__ void classifier_kernel(const float* __restrict__ Hr, const float* __restrict__ Hi,
                                  const float* __restrict__ Wc, const float* __restrict__ bc,
                                  float* __restrict__ out) {
    int row = blockIdx.x;
    int t = threadIdx.x;   // 128
    __shared__ float x[512];
    __shared__ float lg[40];
    for (int i = t; i < 256; i += 128) {
        x[i]       = Hr[row * 256 + i];
        x[i + 256] = Hi[row * 256 + i];
    }
    __syncthreads();
    int warp = t >> 5, lane = t & 31;
    for (int c = warp; c < 40; c += 4) {
        float s = 0.f;
        #pragma unroll
        for (int k = lane; k < 512; k += 32) s = fmaf(x[k], Wc[c * 512 + k], s);
        #pragma unroll
        for (int o = 16; o > 0; o >>= 1) s += __shfl_xor_sync(0xffffffffu, s, o);
        if (lane == 0) lg[c] = s + bc[c];
    }
    __syncthreads();
    if (warp == 0) {
        float a  = (lane < 40)      ? lg[lane]      : -3.4e38f;
        float b2 = (lane + 32 < 40) ? lg[lane + 32] : -3.4e38f;
        float m = fmaxf(a, b2);
        #pragma unroll
        for (int o = 16; o > 0; o >>= 1) m = fmaxf(m, __shfl_xor_sync(0xffffffffu, m, o));
        float s = ((lane < 40) ? expf(a - m) : 0.f) + ((lane + 32 < 40) ? expf(b2 - m) : 0.f);
        #pragma unroll
        for (int o = 16; o > 0; o >>= 1) s += __shfl_xor_sync(0xffffffffu, s, o);
        float lse = m + logf(s);
        if (lane < 40)      out[row * 40 + lane]      = a - lse;
        if (lane + 32 < 40) out[row * 40 + lane + 32] = b2 - lse;
    }
}

// ---------------- launch ----------------
extern "C" void kernel_launch(void* const* d_in, const int* in_sizes, int n_in,
                              void* d_out, int out_size) {
    const float* real = (const float*)d_in[0];
    const float* imag = (const float*)d_in[1];
    const int*   edges = (const int*)d_in[2];
    const float* qp = (const float*)d_in[3];
    const float* ew = (const float*)d_in[4];
    const float* W1 = (const float*)d_in[5];
    const float* b1 = (const float*)d_in[6];
    const float* W2 = (const float*)d_in[7];
    const float* b2 = (const float*)d_in[8];
    const float* Wc = (const float*)d_in[9];
    const float* bc = (const float*)d_in[10];
    float* out = (float*)d_out;
    int E = in_sizes[4];

    float *Z1r, *Z1i, *Z2r, *Z2i, *H1r, *H1i, *H2r, *H2i;
    cudaGetSymbolAddress((void**)&Z1r, g_Z1r);
    cudaGetSymbolAddress((void**)&Z1i, g_Z1i);
    cudaGetSymbolAddress((void**)&Z2r, g_Z2r);
    cudaGetSymbolAddress((void**)&Z2i, g_Z2i);
    cudaGetSymbolAddress((void**)&H1r, g_H1r);
    cudaGetSymbolAddress((void**)&H1i, g_H1i);
    cudaGetSymbolAddress((void**)&H2r, g_H2r);
    cudaGetSymbolAddress((void**)&H2i, g_H2i);

    // graph build
    zero_kernel<<<TSIZE / 256, 256>>>();
    insert_kernel<<<(E + 255) / 256, 256>>>(edges, ew, E);
    dinv_kernel<<<NN / 256, 256>>>();
    emit_kernel<<<EMAX / 256, 256>>>(qp);

    // ---- layer 1 ----
    spmm_kernel<<<NN, 256>>>(real, imag, nullptr, nullptr, Z1r, Z1i);
    spmm_kernel<<<NN, 256>>>(Z1r, Z1i, real, imag, Z2r, Z2i);
    gemm_fused_kernel<<<dim3(4, 64), 256>>>(real, Z1r, Z2r, imag, Z1i, Z2i, W1, b1, H1r, H1i);

    // ---- layer 2 ----
    spmm_kernel<<<NN, 256>>>(H1r, H1i, nullptr, nullptr, Z1r, Z1i);
    spmm_kernel<<<NN, 256>>>(Z1r, Z1i, H1r, H1i, Z2r, Z2i);
    gemm_fused_kernel<<<dim3(4, 64), 256>>>(H1r, Z1r, Z2r, H1i, Z1i, Z2i, W2, b2, H2r, H2i);

    classifier_kernel<<<NN, 128>>>(H2r, H2i, Wc, bc, out);
}